// round 5
// baseline (speedup 1.0000x reference)
#include <cuda_runtime.h>

#define WDIM  64
#define SDIM  512
#define C8    64
#define XST   516   // Xs row stride
#define FGST  132
#define AST   68

__device__ float g_inv_sigma;
// fragment-packed, tf32-pre-rounded weight copies
__device__ float g_whP [262144];  // wh  [512x512]
__device__ float g_wsnP[262144];  // wsn [512x512]
__device__ float g_fgP [65536];   // [wf|wg] packed

__device__ __forceinline__ unsigned f2tf(float f) {
    unsigned r;
    asm("cvt.rna.tf32.f32 %0, %1;" : "=r"(r) : "f"(f));
    return r;
}
__device__ __forceinline__ float rndtf(float f) { return __uint_as_float(f2tf(f)); }
__device__ __forceinline__ unsigned bits(float f) { return __float_as_uint(f); }

__device__ __forceinline__ void mma_tf32(float* c,
                                         unsigned a0, unsigned a1, unsigned a2, unsigned a3,
                                         unsigned b0, unsigned b1) {
    asm volatile(
        "mma.sync.aligned.m16n8k8.row.col.f32.tf32.tf32.f32 "
        "{%0,%1,%2,%3}, {%4,%5,%6,%7}, {%8,%9}, {%0,%1,%2,%3};\n"
        : "+f"(c[0]), "+f"(c[1]), "+f"(c[2]), "+f"(c[3])
        : "r"(a0), "r"(a1), "r"(a2), "r"(a3), "r"(b0), "r"(b1));
}

// ---------------------------------------------------------------------------
// init kernel: blocks 0..511 pack+round weights; block 512 computes sigma.
// ---------------------------------------------------------------------------
__global__ __launch_bounds__(512)
void init_kernel(const float* __restrict__ wf, const float* __restrict__ wg,
                 const float* __restrict__ wh, const float* __restrict__ wsn,
                 const float* __restrict__ usn) {
    if (blockIdx.x < 512) {
        int i = blockIdx.x * 512 + threadIdx.x;   // 0..262143
        {
            int j = i & 3, l = (i >> 2) & 31, h = (i >> 7) & 1, r = (i >> 8) & 1;
            int ng = (i >> 9) & 7, ks = i >> 12;
            int row = ks * 8 + (l & 3) + r * 4;
            int col = ng * 64 + (h * 4 + j) * 8 + (l >> 2);
            g_whP[i]  = rndtf(wh [(size_t)row * SDIM + col]);
            g_wsnP[i] = rndtf(wsn[(size_t)row * SDIM + col]);
        }
        if (i < 65536) {
            int j = i & 3, l = (i >> 2) & 31, r = (i >> 7) & 1;
            int ng = (i >> 8) & 3, ks = i >> 10;
            int row = ks * 8 + (l & 3) + r * 4;
            int col = ng * 32 + j * 8 + (l >> 2);
            g_fgP[i] = rndtf(col < 64 ? wf[(size_t)row * C8 + col]
                                      : wg[(size_t)row * C8 + col - 64]);
        }
        return;
    }
    // ---- sigma (one block) ----
    __shared__ float us[512];
    __shared__ float vs[512];
    __shared__ float red[17];
    int tid = threadIdx.x, wid = tid >> 5, lane = tid & 31;
    us[tid] = usn[tid];
    __syncthreads();

    float q = 0.f;
    for (int rr = 0; rr < 32; rr++) {
        int row = wid * 32 + rr;
        const float4* wr = (const float4*)(wsn + (size_t)row * SDIM);
        const float4* ur = (const float4*)us;
        float s = 0.f;
        #pragma unroll
        for (int i = 0; i < 4; i++) {
            float4 w = wr[lane + i * 32], u = ur[lane + i * 32];
            s += w.x * u.x + w.y * u.y + w.z * u.z + w.w * u.w;
        }
        #pragma unroll
        for (int o = 16; o; o >>= 1) s += __shfl_xor_sync(0xffffffffu, s, o);
        if (lane == 0) { vs[row] = s; q += s * s; }
    }
    if (lane == 0) red[wid] = q;
    __syncthreads();
    if (tid == 0) {
        float z = 0.f;
        for (int i = 0; i < 16; i++) z += red[i];
        red[16] = 1.f / (sqrtf(z) + 1e-12f);
    }
    __syncthreads();
    float inv_nv = red[16];
    __syncthreads();

    float t0 = 0.f, t1 = 0.f, t2 = 0.f, t3 = 0.f;
    for (int i = 0; i < SDIM; i += 4) {
        t0 += vs[i + 0] * wsn[(size_t)(i + 0) * SDIM + tid];
        t1 += vs[i + 1] * wsn[(size_t)(i + 1) * SDIM + tid];
        t2 += vs[i + 2] * wsn[(size_t)(i + 2) * SDIM + tid];
        t3 += vs[i + 3] * wsn[(size_t)(i + 3) * SDIM + tid];
    }
    float tj = ((t0 + t1) + (t2 + t3)) * inv_nv;
    float q2 = tj * tj;
    #pragma unroll
    for (int o = 16; o; o >>= 1) q2 += __shfl_xor_sync(0xffffffffu, q2, o);
    if (lane == 0) red[wid] = q2;
    __syncthreads();
    if (tid == 0) {
        float z = 0.f;
        for (int i = 0; i < 16; i++) z += red[i];
        float nt = sqrtf(z);
        g_inv_sigma = (nt + 1e-12f) / z;
    }
}

// ---------------------------------------------------------------------------
// 32-warp MMA block: acc[2][4][4] += A(64xK) @ Wpacked, NKS k-steps.
// wp = warp fragment base (ng64/h/lane folded in); per-k-step stride 1024 uint4.
// ---------------------------------------------------------------------------
template <int STRIDE, int NKS>
__device__ __forceinline__ void mma_block32(float (&acc)[2][4][4],
                                            const float* __restrict__ A,
                                            const uint4* __restrict__ wp,
                                            int mg, int g, int t) {
    #pragma unroll 4
    for (int ks = 0; ks < NKS; ks++) {
        const uint4* p = wp + (size_t)ks * 1024;
        uint4 Bv0 = p[0];    // r=0: b0 for nj 0..3
        uint4 Bv1 = p[64];   // r=1: b1 for nj 0..3
        unsigned b0[4] = {Bv0.x, Bv0.y, Bv0.z, Bv0.w};
        unsigned b1[4] = {Bv1.x, Bv1.y, Bv1.z, Bv1.w};
        int k = ks * 8;
        #pragma unroll
        for (int mi = 0; mi < 2; mi++) {
            int r = mg * 32 + mi * 16 + g;
            unsigned a0 = bits(A[r * STRIDE + k + t]);
            unsigned a1 = bits(A[(r + 8) * STRIDE + k + t]);
            unsigned a2 = bits(A[r * STRIDE + k + t + 4]);
            unsigned a3 = bits(A[(r + 8) * STRIDE + k + t + 4]);
            #pragma unroll
            for (int nj = 0; nj < 4; nj++)
                mma_tf32(acc[mi][nj], a0, a1, a2, a3, b0[nj], b1[nj]);
        }
    }
}

// ---------------------------------------------------------------------------
extern __shared__ float smf[];

__global__ __launch_bounds__(1024, 1)
void fused_kernel(const float* __restrict__ x,
                  const float* __restrict__ bf, const float* __restrict__ bg,
                  const float* __restrict__ bh,
                  const float* __restrict__ gamma,
                  const float* __restrict__ ln1g, const float* __restrict__ ln1b,
                  const float* __restrict__ ln2g, const float* __restrict__ ln2b,
                  float* __restrict__ out) {
    float* Xs     = smf;                    // 64 x 516
    float* FGs    = Xs + 64 * XST;          // 64 x 132
    float* ATTs   = FGs + 64 * FGST;        // 64 x 68
    float* AXs    = ATTs + 64 * AST;        // 2 x (64 x 68)
    float* rowsum = AXs + 2 * 64 * AST;     // 64
    float* stats  = rowsum + 64;            // 128

    const int tid  = threadIdx.x;
    const int wid  = tid >> 5;              // 0..31
    const int lane = tid & 31;
    const int g    = lane >> 2;
    const int t    = lane & 3;
    const size_t base = (size_t)blockIdx.x * (WDIM * SDIM);

    // ---- load X, pre-rounded to tf32 ----
    for (int i = tid; i < WDIM * SDIM / 4; i += 1024) {
        float4 v = ((const float4*)(x + base))[i];
        int r = i >> 7;
        int c = (i & 127) * 4;
        float* p = &Xs[r * XST + c];
        p[0] = rndtf(v.x); p[1] = rndtf(v.y); p[2] = rndtf(v.z); p[3] = rndtf(v.w);
    }
    __syncthreads();

    // ---- GEMM1: [F|G] = X @ [Wf|Wg] + bias   (32 warps: 4m x 8n, 16x16 tiles) ----
    {
        const int mg1 = wid & 3;
        const int ng1 = wid >> 2;           // 0..7, 16 cols each
        const int ngOld = ng1 >> 1, jsel = ng1 & 1;
        const uint2* fgp = reinterpret_cast<const uint2*>(g_fgP)
                         + (size_t)ngOld * 128 + lane * 2 + jsel;
        float acc1[2][4];
        #pragma unroll
        for (int nj = 0; nj < 2; nj++)
            #pragma unroll
            for (int c = 0; c < 4; c++) acc1[nj][c] = 0.f;

        const int rA = mg1 * 16 + g;
        #pragma unroll 4
        for (int ks = 0; ks < 64; ks++) {
            const uint2* p = fgp + (size_t)ks * 512;
            uint2 B0 = p[0];     // r=0 -> b0 (k+t)
            uint2 B1 = p[64];    // r=1 -> b1 (k+t+4)
            int k = ks * 8;
            unsigned a0 = bits(Xs[rA * XST + k + t]);
            unsigned a1 = bits(Xs[(rA + 8) * XST + k + t]);
            unsigned a2 = bits(Xs[rA * XST + k + t + 4]);
            unsigned a3 = bits(Xs[(rA + 8) * XST + k + t + 4]);
            mma_tf32(acc1[0], a0, a1, a2, a3, B0.x, B1.x);
            mma_tf32(acc1[1], a0, a1, a2, a3, B0.y, B1.y);
        }
        #pragma unroll
        for (int nj = 0; nj < 2; nj++) {
            int cg = ng1 * 16 + nj * 8 + 2 * t;
            float bias0 = (cg < 64) ? bf[cg] : bg[cg - 64];
            float bias1 = (cg + 1 < 64) ? bf[cg + 1] : bg[cg + 1 - 64];
            FGs[rA * FGST + cg]           = rndtf(acc1[nj][0] + bias0);
            FGs[rA * FGST + cg + 1]       = rndtf(acc1[nj][1] + bias1);
            FGs[(rA + 8) * FGST + cg]     = rndtf(acc1[nj][2] + bias0);
            FGs[(rA + 8) * FGST + cg + 1] = rndtf(acc1[nj][3] + bias1);
        }
    }
    __syncthreads();

    const int mq = wid & 3;                 // 16-row tiles for GEMM2/3
    const int n8 = (wid >> 2) * 8;          // 8-col tiles

    // ---- GEMM2: ATT = sigmoid(F @ G^T)   (32 warps: 4m x 8n) ----
    {
        float acc2[4] = {0.f, 0.f, 0.f, 0.f};
        #pragma unroll
        for (int k = 0; k < 64; k += 8) {
            unsigned b0 = bits(FGs[(n8 + g) * FGST + 64 + k + t]);
            unsigned b1 = bits(FGs[(n8 + g) * FGST + 64 + k + t + 4]);
            int r = mq * 16 + g;
            unsigned a0 = bits(FGs[r * FGST + k + t]);
            unsigned a1 = bits(FGs[(r + 8) * FGST + k + t]);
            unsigned a2 = bits(FGs[r * FGST + k + t + 4]);
            unsigned a3 = bits(FGs[(r + 8) * FGST + k + t + 4]);
            mma_tf32(acc2, a0, a1, a2, a3, b0, b1);
        }
        int r = mq * 16 + g;
        ATTs[r * AST + n8 + 2 * t]           = rndtf(1.f / (1.f + __expf(-acc2[0])));
        ATTs[r * AST + n8 + 2 * t + 1]       = rndtf(1.f / (1.f + __expf(-acc2[1])));
        ATTs[(r + 8) * AST + n8 + 2 * t]     = rndtf(1.f / (1.f + __expf(-acc2[2])));
        ATTs[(r + 8) * AST + n8 + 2 * t + 1] = rndtf(1.f / (1.f + __expf(-acc2[3])));
    }
    __syncthreads();

    if (tid < 64) {
        float s = 0.f;
        for (int v = 0; v < 64; v++) s += ATTs[tid * AST + v];
        rowsum[tid] = s;
    }

    // ---- GEMM3+4 fused: ATTN = (ATT @ X) @ Wh  (GEMM4: 2m x 16n warps) ----
    const int mg   = wid & 1;
    const int ng   = wid >> 1;              // 0..15, 32 cols each
    const int ng64 = ng >> 1, h = ng & 1;
    const uint4* whpW  = reinterpret_cast<const uint4*>(g_whP)
                       + (size_t)ng64 * 128 + h * 32 + lane;
    const uint4* wsnpW = reinterpret_cast<const uint4*>(g_wsnP)
                       + (size_t)ng64 * 128 + h * 32 + lane;

    float acc[2][4][4];
    #pragma unroll
    for (int mi = 0; mi < 2; mi++)
        #pragma unroll
        for (int nj = 0; nj < 4; nj++)
            #pragma unroll
            for (int c = 0; c < 4; c++) acc[mi][nj][c] = 0.f;

    for (int kc = 0; kc < 8; kc++) {
        const int cb = kc * 64;
        float* AXb = AXs + (kc & 1) * 64 * AST;

        // GEMM3: AXc = ATT @ X[:, cb:cb+64]  (4m x 8n warps)
        float axc[4] = {0.f, 0.f, 0.f, 0.f};
        #pragma unroll
        for (int k = 0; k < 64; k += 8) {
            unsigned b0 = bits(Xs[(k + t) * XST + cb + n8 + g]);
            unsigned b1 = bits(Xs[(k + t + 4) * XST + cb + n8 + g]);
            int r = mq * 16 + g;
            unsigned a0 = bits(ATTs[r * AST + k + t]);
            unsigned a1 = bits(ATTs[(r + 8) * AST + k + t]);
            unsigned a2 = bits(ATTs[r * AST + k + t + 4]);
            unsigned a3 = bits(ATTs[(r + 8) * AST + k + t + 4]);
            mma_tf32(axc, a0, a1, a2, a3, b0, b1);
        }
        {
            int r = mq * 16 + g;
            AXb[r * AST + n8 + 2 * t]           = rndtf(axc[0]);
            AXb[r * AST + n8 + 2 * t + 1]       = rndtf(axc[1]);
            AXb[(r + 8) * AST + n8 + 2 * t]     = rndtf(axc[2]);
            AXb[(r + 8) * AST + n8 + 2 * t + 1] = rndtf(axc[3]);
        }
        __syncthreads();

        mma_block32<AST, 8>(acc, AXb, whpW + (size_t)(kc * 8) * 1024, mg, g, t);
    }

    // ---- epilogue 1: Xs = gamma*(attn + rowsum*bh)  (x added in LN1 pass) ----
    {
        float gam = gamma[0];
        #pragma unroll
        for (int mi = 0; mi < 2; mi++) {
            int r0 = mg * 32 + mi * 16 + g, r1 = r0 + 8;
            float rs0 = rowsum[r0], rs1 = rowsum[r1];
            #pragma unroll
            for (int nj = 0; nj < 4; nj++) {
                int c0 = ng * 32 + nj * 8 + 2 * t;
                float bh0 = bh[c0], bh1 = bh[c0 + 1];
                Xs[r0 * XST + c0]     = gam * (acc[mi][nj][0] + rs0 * bh0);
                Xs[r0 * XST + c0 + 1] = gam * (acc[mi][nj][1] + rs0 * bh1);
                Xs[r1 * XST + c0]     = gam * (acc[mi][nj][2] + rs1 * bh0);
                Xs[r1 * XST + c0 + 1] = gam * (acc[mi][nj][3] + rs1 * bh1);
            }
        }
    }
    __syncthreads();

    // ---- LN1 pass1: add residual x (re-read), accumulate stats ----
    {
        int row = tid >> 4, j0 = tid & 15;
        const float4* xr = (const float4*)(x + base + (size_t)row * SDIM);
        float4* Xr = (float4*)(Xs + row * XST);
        float s = 0.f, sq = 0.f;
        #pragma unroll
        for (int i = 0; i < 8; i++) {
            int c4 = j0 + i * 16;
            float4 v = Xr[c4];
            float4 xv = xr[c4];
            v.x += xv.x; v.y += xv.y; v.z += xv.z; v.w += xv.w;
            Xr[c4] = v;
            s  += (v.x + v.y) + (v.z + v.w);
            sq += (v.x * v.x + v.y * v.y) + (v.z * v.z + v.w * v.w);
        }
        #pragma unroll
        for (int o = 1; o <= 8; o <<= 1) {
            s  += __shfl_xor_sync(0xffffffffu, s, o);
            sq += __shfl_xor_sync(0xffffffffu, sq, o);
        }
        if (j0 == 0) {
            float mean = s * (1.f / SDIM);
            float var  = sq * (1.f / SDIM) - mean * mean;
            stats[row * 2]     = mean;
            stats[row * 2 + 1] = rsqrtf(var + 1e-6f);
        }
    }
    __syncthreads();
    // ---- LN1 pass2: normalize, pre-round (feeds GEMM5 only) ----
    {
        int row = tid >> 4, j0 = tid & 15;
        float mean = stats[row * 2], rstd = stats[row * 2 + 1];
        float4* Xr = (float4*)(Xs + row * XST);
        #pragma unroll
        for (int i = 0; i < 8; i++) {
            int c4 = j0 + i * 16;
            float4 v = Xr[c4];
            float4 gv = ((const float4*)ln1g)[c4];
            float4 bv = ((const float4*)ln1b)[c4];
            v.x = rndtf((v.x - mean) * rstd * gv.x + bv.x);
            v.y = rndtf((v.y - mean) * rstd * gv.y + bv.y);
            v.z = rndtf((v.z - mean) * rstd * gv.z + bv.z);
            v.w = rndtf((v.w - mean) * rstd * gv.w + bv.w);
            Xr[c4] = v;
        }
    }
    __syncthreads();

    // ---- GEMM5: Y = out1 @ Wsn ----
    #pragma unroll
    for (int mi = 0; mi < 2; mi++)
        #pragma unroll
        for (int nj = 0; nj < 4; nj++)
            #pragma unroll
            for (int c = 0; c < 4; c++) acc[mi][nj][c] = 0.f;

    mma_block32<XST, 64>(acc, Xs, wsnpW, mg, g, t);
    __syncthreads();

    // ---- epilogue 2: relu(acc/sigma) -> Xs ----
    {
        float invsig = g_inv_sigma;
        #pragma unroll
        for (int mi = 0; mi < 2; mi++) {
            int r0 = mg * 32 + mi * 16 + g, r1 = r0 + 8;
            #pragma unroll
            for (int nj = 0; nj < 4; nj++) {
                int c0 = ng * 32 + nj * 8 + 2 * t;
                Xs[r0 * XST + c0]     = fmaxf(acc[mi][nj][0] * invsig, 0.f);
                Xs[r0 * XST + c0 + 1] = fmaxf(acc[mi][nj][1] * invsig, 0.f);
                Xs[r1 * XST + c0]     = fmaxf(acc[mi][nj][2] * invsig, 0.f);
                Xs[r1 * XST + c0 + 1] = fmaxf(acc[mi][nj][3] * invsig, 0.f);
            }
        }
    }
    __syncthreads();

    // ---- LN2 pass1 ----
    {
        int row = tid >> 4, j0 = tid & 15;
        const float4* Xr = (const float4*)(Xs + row * XST);
        float s = 0.f, sq = 0.f;
        #pragma unroll
        for (int i = 0; i < 8; i++) {
            float4 v = Xr[j0 + i * 16];
            s  += (v.x + v.y) + (v.z + v.w);
            sq += (v.x * v.x + v.y * v.y) + (v.z * v.z + v.w * v.w);
        }
        #pragma unroll
        for (int o = 1; o <= 8; o <<= 1) {
            s  += __shfl_xor_sync(0xffffffffu, s, o);
            sq += __shfl_xor_sync(0xffffffffu, sq, o);
        }
        if (j0 == 0) {
            float mean = s * (1.f / SDIM);
            float var  = sq * (1.f / SDIM) - mean * mean;
            stats[row * 2]     = mean;
            stats[row * 2 + 1] = rsqrtf(var + 1e-6f);
        }
    }
    __syncthreads();
    // ---- LN2 pass2 -> global out ----
    {
        int row = tid >> 4, j0 = tid & 15;
        float mean = stats[row * 2], rstd = stats[row * 2 + 1];
        const float4* Xr = (const float4*)(Xs + row * XST);
        float4* orow = (float4*)(out + base + (size_t)row * SDIM);
        #pragma unroll
        for (int i = 0; i < 8; i++) {
            int c4 = j0 + i * 16;
            float4 v = Xr[c4];
            float4 gv = ((const float4*)ln2g)[c4];
            float4 bv = ((const float4*)ln2b)[c4];
            v.x = (v.x - mean) * rstd * gv.x + bv.x;
            v.y = (v.y - mean) * rstd * gv.y + bv.y;
            v.z = (v.z - mean) * rstd * gv.z + bv.z;
            v.w = (v.w - mean) * rstd * gv.w + bv.w;
            orow[c4] = v;
        }
    }
}

// ---------------------------------------------------------------------------
extern "C" void kernel_launch(void* const* d_in, const int* in_sizes, int n_in,
                              void* d_out, int out_size) {
    (void)in_sizes; (void)n_in; (void)out_size;
    const float* x    = (const float*)d_in[0];
    const float* wf   = (const float*)d_in[1];
    const float* bf   = (const float*)d_in[2];
    const float* wg   = (const float*)d_in[3];
    const float* bg   = (const float*)d_in[4];
    const float* wh   = (const float*)d_in[5];
    const float* bh   = (const float*)d_in[6];
    const float* gam  = (const float*)d_in[7];
    const float* ln1g = (const float*)d_in[8];
    const float* ln1b = (const float*)d_in[9];
    const float* wsn  = (const float*)d_in[10];
    const float* usn  = (const float*)d_in[11];
    const float* ln2g = (const float*)d_in[12];
    const float* ln2b = (const float*)d_in[13];
    float* out = (float*)d_out;

    init_kernel<<<513, 512>>>(wf, wg, wh, wsn, usn);

    const int smem_bytes = (64 * XST + 64 * FGST + 64 * AST + 2 * 64 * AST + 64 + 128) * 4;
    cudaFuncSetAttribute(fused_kernel, cudaFuncAttributeMaxDynamicSharedMemorySize, smem_bytes);
    fused_kernel<<<1024, 1024, smem_bytes>>>(x, bf, bg, bh, gam,
                                             ln1g, ln1b, ln2g, ln2b, out);
}

// round 7
// speedup vs baseline: 1.1677x; 1.1677x over previous
#include <cuda_runtime.h>

#define WDIM  64
#define SDIM  512
#define C8    64
#define ROWST 516   // row-major phase stride (words)
#define FGST  132
#define PXF   132   // packed fragment stride (words); 128 data + 4 pad

// SMEM word offsets
#define FG_OFF  33792              // after packed X: 4*64 frags * 132
#define ATT_OFF (FG_OFF + 8448)    // 64x132
#define AX_OFF  (ATT_OFF + 4224)   // 32 frags * 132
#define RS_OFF  (AX_OFF + 8448)    // 2 buffers
#define ST_OFF  (RS_OFF + 64)
#define SM_TOT  (ST_OFF + 128)     // 55104 words = 220416 B

__device__ float g_inv_sigma;
__device__ float g_whP [262144];
__device__ float g_wsnP[262144];
__device__ float g_fgP [65536];

__device__ __forceinline__ unsigned f2tf(float f) {
    unsigned r;
    asm("cvt.rna.tf32.f32 %0, %1;" : "=r"(r) : "f"(f));
    return r;
}
__device__ __forceinline__ float rndtf(float f) { return __uint_as_float(f2tf(f)); }
__device__ __forceinline__ unsigned bits(float f) { return __float_as_uint(f); }

__device__ __forceinline__ void mma_tf32(float* c,
                                         unsigned a0, unsigned a1, unsigned a2, unsigned a3,
                                         unsigned b0, unsigned b1) {
    asm volatile(
        "mma.sync.aligned.m16n8k8.row.col.f32.tf32.tf32.f32 "
        "{%0,%1,%2,%3}, {%4,%5,%6,%7}, {%8,%9}, {%0,%1,%2,%3};\n"
        : "+f"(c[0]), "+f"(c[1]), "+f"(c[2]), "+f"(c[3])
        : "r"(a0), "r"(a1), "r"(a2), "r"(a3), "r"(b0), "r"(b1));
}

// ---------------------------------------------------------------------------
__global__ __launch_bounds__(512)
void init_kernel(const float* __restrict__ wf, const float* __restrict__ wg,
                 const float* __restrict__ wh, const float* __restrict__ wsn,
                 const float* __restrict__ usn) {
    if (blockIdx.x < 512) {
        int i = blockIdx.x * 512 + threadIdx.x;
        {
            int j = i & 3, l = (i >> 2) & 31, h = (i >> 7) & 1, r = (i >> 8) & 1;
            int ng = (i >> 9) & 7, ks = i >> 12;
            int row = ks * 8 + (l & 3) + r * 4;
            int col = ng * 64 + (h * 4 + j) * 8 + (l >> 2);
            g_whP[i]  = rndtf(wh [(size_t)row * SDIM + col]);
            g_wsnP[i] = rndtf(wsn[(size_t)row * SDIM + col]);
        }
        if (i < 65536) {
            int j = i & 3, l = (i >> 2) & 31, r = (i >> 7) & 1;
            int ng = (i >> 8) & 3, ks = i >> 10;
            int row = ks * 8 + (l & 3) + r * 4;
            int col = ng * 32 + j * 8 + (l >> 2);
            g_fgP[i] = rndtf(col < 64 ? wf[(size_t)row * C8 + col]
                                      : wg[(size_t)row * C8 + col - 64]);
        }
        return;
    }
    __shared__ float us[512];
    __shared__ float vs[512];
    __shared__ float red[17];
    int tid = threadIdx.x, wid = tid >> 5, lane = tid & 31;
    us[tid] = usn[tid];
    __syncthreads();

    float q = 0.f;
    for (int rr = 0; rr < 32; rr++) {
        int row = wid * 32 + rr;
        const float4* wr = (const float4*)(wsn + (size_t)row * SDIM);
        const float4* ur = (const float4*)us;
        float s = 0.f;
        #pragma unroll
        for (int i = 0; i < 4; i++) {
            float4 w = wr[lane + i * 32], u = ur[lane + i * 32];
            s += w.x * u.x + w.y * u.y + w.z * u.z + w.w * u.w;
        }
        #pragma unroll
        for (int o = 16; o; o >>= 1) s += __shfl_xor_sync(0xffffffffu, s, o);
        if (lane == 0) { vs[row] = s; q += s * s; }
    }
    if (lane == 0) red[wid] = q;
    __syncthreads();
    if (tid == 0) {
        float z = 0.f;
        for (int i = 0; i < 16; i++) z += red[i];
        red[16] = 1.f / (sqrtf(z) + 1e-12f);
    }
    __syncthreads();
    float inv_nv = red[16];
    __syncthreads();

    float t0 = 0.f, t1 = 0.f, t2 = 0.f, t3 = 0.f;
    for (int i = 0; i < SDIM; i += 4) {
        t0 += vs[i + 0] * wsn[(size_t)(i + 0) * SDIM + tid];
        t1 += vs[i + 1] * wsn[(size_t)(i + 1) * SDIM + tid];
        t2 += vs[i + 2] * wsn[(size_t)(i + 2) * SDIM + tid];
        t3 += vs[i + 3] * wsn[(size_t)(i + 3) * SDIM + tid];
    }
    float tj = ((t0 + t1) + (t2 + t3)) * inv_nv;
    float q2 = tj * tj;
    #pragma unroll
    for (int o = 16; o; o >>= 1) q2 += __shfl_xor_sync(0xffffffffu, q2, o);
    if (lane == 0) red[wid] = q2;
    __syncthreads();
    if (tid == 0) {
        float z = 0.f;
        for (int i = 0; i < 16; i++) z += red[i];
        float nt = sqrtf(z);
        g_inv_sigma = (nt + 1e-12f) / z;
    }
}

// ---------------------------------------------------------------------------
// GEMM with packed-fragment A (LDS.128) + packed weights (LDG.128).
// FSTEP = frags per (mg*2+mi) group (8 for AX chunks, 64 for full X).
// ---------------------------------------------------------------------------
template <int FSTEP, int NKS>
__device__ __forceinline__ void mma_block_frag(float (&acc)[2][8][4],
                                               const float* __restrict__ Ap,
                                               const uint4* __restrict__ wp,
                                               int mg, int lane) {
    #pragma unroll 2
    for (int ks = 0; ks < NKS; ks++) {
        const uint4* p = wp + (size_t)ks * 1024;
        uint4 Bv0 = p[0];
        uint4 Bv1 = p[32];
        uint4 Bv2 = p[64];
        uint4 Bv3 = p[96];
        unsigned b0[8] = {Bv0.x, Bv0.y, Bv0.z, Bv0.w, Bv1.x, Bv1.y, Bv1.z, Bv1.w};
        unsigned b1[8] = {Bv2.x, Bv2.y, Bv2.z, Bv2.w, Bv3.x, Bv3.y, Bv3.z, Bv3.w};
        #pragma unroll
        for (int mi = 0; mi < 2; mi++) {
            float4 av = ((const float4*)Ap)[(size_t)((mg * 2 + mi) * FSTEP + ks) * 33 + lane];
            unsigned a0 = bits(av.x), a1 = bits(av.y), a2 = bits(av.z), a3 = bits(av.w);
            #pragma unroll
            for (int nj = 0; nj < 8; nj++)
                mma_tf32(acc[mi][nj], a0, a1, a2, a3, b0[nj], b1[nj]);
        }
    }
}

// Scalar-A GEMM (row-major A), used for GEMM5.
template <int STRIDE, int NKS>
__device__ __forceinline__ void mma_block_scalar(float (&acc)[2][8][4],
                                                 const float* __restrict__ A,
                                                 const uint4* __restrict__ wp,
                                                 int mg, int g, int t) {
    #pragma unroll 2
    for (int ks = 0; ks < NKS; ks++) {
        const uint4* p = wp + (size_t)ks * 1024;
        uint4 Bv0 = p[0];
        uint4 Bv1 = p[32];
        uint4 Bv2 = p[64];
        uint4 Bv3 = p[96];
        unsigned b0[8] = {Bv0.x, Bv0.y, Bv0.z, Bv0.w, Bv1.x, Bv1.y, Bv1.z, Bv1.w};
        unsigned b1[8] = {Bv2.x, Bv2.y, Bv2.z, Bv2.w, Bv3.x, Bv3.y, Bv3.z, Bv3.w};
        int k = ks * 8;
        #pragma unroll
        for (int mi = 0; mi < 2; mi++) {
            int r = mg * 32 + mi * 16 + g;
            unsigned a0 = bits(A[r * STRIDE + k + t]);
            unsigned a1 = bits(A[(r + 8) * STRIDE + k + t]);
            unsigned a2 = bits(A[r * STRIDE + k + t + 4]);
            unsigned a3 = bits(A[(r + 8) * STRIDE + k + t + 4]);
            #pragma unroll
            for (int nj = 0; nj < 8; nj++)
                mma_tf32(acc[mi][nj], a0, a1, a2, a3, b0[nj], b1[nj]);
        }
    }
}

// ---------------------------------------------------------------------------
extern __shared__ float smf[];

__global__ __launch_bounds__(512, 1)
void fused_kernel(const float* __restrict__ x,
                  const float* __restrict__ bf, const float* __restrict__ bg,
                  const float* __restrict__ bh,
                  const float* __restrict__ gamma,
                  const float* __restrict__ ln1g, const float* __restrict__ ln1b,
                  const float* __restrict__ ln2g, const float* __restrict__ ln2b,
                  float* __restrict__ out) {
    float* Xs     = smf;             // packed X (phase 1) / row-major 64x516 (phase 2)
    float* FGs    = smf + FG_OFF;    // 64 x 132 row-major
    float* ATTp   = smf + ATT_OFF;   // packed 32 frags
    float* AXp    = smf + AX_OFF;    // packed, 2 buffers of 32 frags
    float* rowsum = smf + RS_OFF;
    float* stats  = smf + ST_OFF;

    const int tid  = threadIdx.x;
    const int wid  = tid >> 5;
    const int lane = tid & 31;
    const int g    = lane >> 2;
    const int t    = lane & 3;
    const size_t base = (size_t)blockIdx.x * (WDIM * SDIM);

    // ---- load X -> packed fragment layout, pre-rounded ----
    // word(R,C) = ((R>>4)*64 + (C>>3))*PXF + ((R&7)*4 + (C&3))*4 + ((R>>3)&1) + 2*((C>>2)&1)
    for (int i = tid; i < WDIM * SDIM / 4; i += 512) {
        float4 v = ((const float4*)(x + base))[i];
        int r = i >> 7;
        int c = (i & 127) << 2;      // multiple of 4
        int b = ((r >> 4) * 64 + (c >> 3)) * PXF + (r & 7) * 16
              + ((r >> 3) & 1) + 2 * ((c >> 2) & 1);
        Xs[b]      = rndtf(v.x);
        Xs[b + 4]  = rndtf(v.y);
        Xs[b + 8]  = rndtf(v.z);
        Xs[b + 12] = rndtf(v.w);
    }
    __syncthreads();

    // ---- GEMM1: [F|G] = X @ [Wf|Wg] + bias  (A via LDS.128 frags) ----
    {
        const int mg1 = wid & 3;
        const int ng1 = wid >> 2;
        const float4* Af1 = (const float4*)Xs + (size_t)mg1 * 64 * 33 + lane;
        const uint4* fgp = (const uint4*)g_fgP + (size_t)(ng1 * 2) * 32 + lane;
        float acc1[4][4];
        #pragma unroll
        for (int nj = 0; nj < 4; nj++)
            #pragma unroll
            for (int c = 0; c < 4; c++) acc1[nj][c] = 0.f;

        const int rA = mg1 * 16 + g;
        #pragma unroll 2
        for (int ks = 0; ks < 64; ks++) {
            const uint4* p = fgp + (size_t)ks * 256;
            uint4 B0 = p[0];
            uint4 B1 = p[32];
            unsigned b0[4] = {B0.x, B0.y, B0.z, B0.w};
            unsigned b1[4] = {B1.x, B1.y, B1.z, B1.w};
            float4 av = Af1[(size_t)ks * 33];
            unsigned a0 = bits(av.x), a1 = bits(av.y), a2 = bits(av.z), a3 = bits(av.w);
            #pragma unroll
            for (int nj = 0; nj < 4; nj++)
                mma_tf32(acc1[nj], a0, a1, a2, a3, b0[nj], b1[nj]);
        }
        #pragma unroll
        for (int nj = 0; nj < 4; nj++) {
            int cg = ng1 * 32 + nj * 8 + 2 * t;
            float bias0 = (cg < 64) ? bf[cg] : bg[cg - 64];
            float bias1 = (cg + 1 < 64) ? bf[cg + 1] : bg[cg + 1 - 64];
            FGs[rA * FGST + cg]           = rndtf(acc1[nj][0] + bias0);
            FGs[rA * FGST + cg + 1]       = rndtf(acc1[nj][1] + bias1);
            FGs[(rA + 8) * FGST + cg]     = rndtf(acc1[nj][2] + bias0);
            FGs[(rA + 8) * FGST + cg + 1] = rndtf(acc1[nj][3] + bias1);
        }
    }
    __syncthreads();

    const int mhalf = wid >> 3;
    const int n8    = (wid & 7) * 8;
    const int fb8   = n8 >> 3;

    // ---- GEMM2: ATT = sigmoid(F @ G^T) -> packed ATTp ----
    {
        float acc2[2][4];
        #pragma unroll
        for (int mi = 0; mi < 2; mi++)
            #pragma unroll
            for (int c = 0; c < 4; c++) acc2[mi][c] = 0.f;

        #pragma unroll
        for (int k = 0; k < 64; k += 8) {
            unsigned b0 = bits(FGs[(n8 + g) * FGST + 64 + k + t]);
            unsigned b1 = bits(FGs[(n8 + g) * FGST + 64 + k + t + 4]);
            #pragma unroll
            for (int mi = 0; mi < 2; mi++) {
                int r = (mhalf * 2 + mi) * 16 + g;
                unsigned a0 = bits(FGs[r * FGST + k + t]);
                unsigned a1 = bits(FGs[(r + 8) * FGST + k + t]);
                unsigned a2 = bits(FGs[r * FGST + k + t + 4]);
                unsigned a3 = bits(FGs[(r + 8) * FGST + k + t + 4]);
                mma_tf32(acc2[mi], a0, a1, a2, a3, b0, b1);
            }
        }
        #pragma unroll
        for (int mi = 0; mi < 2; mi++) {
            int f = (mhalf * 2 + mi) * 8 + fb8;
            int w0 = f * PXF + (g * 4 + 2 * (t & 1)) * 4 + 2 * (t >> 1);
            ATTp[w0]     = rndtf(1.f / (1.f + __expf(-acc2[mi][0])));
            ATTp[w0 + 4] = rndtf(1.f / (1.f + __expf(-acc2[mi][1])));
            ATTp[w0 + 1] = rndtf(1.f / (1.f + __expf(-acc2[mi][2])));
            ATTp[w0 + 5] = rndtf(1.f / (1.f + __expf(-acc2[mi][3])));
        }
    }
    __syncthreads();

    if (tid < 64) {
        int R = tid;
        int inner = (R & 7) * 16 + ((R >> 3) & 1);
        int frb = (R >> 4) * 8;
        float s = 0.f;
        for (int v = 0; v < 64; v++) {
            int w = (frb + (v >> 3)) * PXF + inner + (v & 3) * 4 + 2 * ((v >> 2) & 1);
            s += ATTp[w];
        }
        rowsum[R] = s;
    }

    // ---- GEMM3+4 fused: ATTN = (ATT @ X) @ Wh ----
    const int mg = wid & 1;
    const int ng = wid >> 1;
    const uint4* whpW  = (const uint4*)g_whP  + (size_t)(ng * 4) * 32 + lane;
    const uint4* wsnpW = (const uint4*)g_wsnP + (size_t)(ng * 4) * 32 + lane;

    float acc[2][8][4];
    #pragma unroll
    for (int mi = 0; mi < 2; mi++)
        #pragma unroll
        for (int nj = 0; nj < 8; nj++)
            #pragma unroll
            for (int c = 0; c < 4; c++) acc[mi][nj][c] = 0.f;

    for (int kc = 0; kc < 8; kc++) {
        float* AXb = AXp + (kc & 1) * 4224;
        const int C3 = kc * 8 + fb8;

        float axc[2][4];
        #pragma unroll
        for (int mi = 0; mi < 2; mi++)
            #pragma unroll
            for (int c = 0; c < 4; c++) axc[mi][c] = 0.f;

        #pragma unroll
        for (int ks = 0; ks < 8; ks++) {
            int k = ks * 8;
            // B from packed X: element (R=k+t, C=cb+n8+g)
            int wb0 = ((k >> 4) * 64 + C3) * PXF + t * 16 + (g & 3) * 4
                    + ((k >> 3) & 1) + 2 * ((g >> 2) & 1);
            unsigned b0 = bits(Xs[wb0]);
            unsigned b1 = bits(Xs[wb0 + 64]);
            #pragma unroll
            for (int mi = 0; mi < 2; mi++) {
                float4 av = ((const float4*)ATTp)[(size_t)((mhalf * 2 + mi) * 8 + ks) * 33 + lane];
                mma_tf32(axc[mi], bits(av.x), bits(av.y), bits(av.z), bits(av.w), b0, b1);
            }
        }
        #pragma unroll
        for (int mi = 0; mi < 2; mi++) {
            int f = (mhalf * 2 + mi) * 8 + fb8;
            int w0 = f * PXF + (g * 4 + 2 * (t & 1)) * 4 + 2 * (t >> 1);
            AXb[w0]     = rndtf(axc[mi][0]);
            AXb[w0 + 4] = rndtf(axc[mi][1]);
            AXb[w0 + 1] = rndtf(axc[mi][2]);
            AXb[w0 + 5] = rndtf(axc[mi][3]);
        }
        __syncthreads();

        mma_block_frag<8, 8>(acc, AXb, whpW + (size_t)(kc * 8) * 1024, mg, lane);
    }

    // ---- epilogue 1: Xs (row-major now) = gamma*(attn + rowsum*bh) ----
    {
        float gam = gamma[0];
        #pragma unroll
        for (int mi = 0; mi < 2; mi++) {
            int r0 = mg * 32 + mi * 16 + g, r1 = r0 + 8;
            float rs0 = rowsum[r0], rs1 = rowsum[r1];
            #pragma unroll
            for (int nj = 0; nj < 8; nj++) {
                int c0 = ng * 64 + nj * 8 + 2 * t;          // FIX: ng*64 (was ng*32)
                float bh0 = bh[c0], bh1 = bh[c0 + 1];
                Xs[r0 * ROWST + c0]     = gam * (acc[mi][nj][0] + rs0 * bh0);
                Xs[r0 * ROWST + c0 + 1] = gam * (acc[mi][nj][1] + rs0 * bh1);
                Xs[r1 * ROWST + c0]     = gam * (acc[mi][nj][2] + rs1 * bh0);
                Xs[r1 * ROWST + c0 + 1] = gam * (acc[mi][nj][3] + rs1 * bh1);
            }
        }
    }
    __syncthreads();

    // ---- LN1 pass1: add residual x, stats ----
    {
        int row = tid >> 3, j0 = tid & 7;
        const float4* xr = (const float4*)(x + base + (size_t)row * SDIM);
        float4* Xr = (float4*)(Xs + row * ROWST);
        float s = 0.f, sq = 0.f;
        #pragma unroll
        for (int i = 0; i < 16; i++) {
            int c4 = j0 + i * 8;
            float4 v = Xr[c4];
            float4 xv = xr[c4];
            v.x += xv.x; v.y += xv.y; v.z += xv.z; v.w += xv.w;
            Xr[c4] = v;
            s  += (v.x + v.y) + (v.z + v.w);
            sq += (v.x * v.x + v.y * v.y) + (v.z * v.z + v.w * v.w);
        }
        #pragma unroll
        for (int o = 1; o <= 4; o <<= 1) {
            s  += __shfl_xor_sync(0xffffffffu, s, o);
            sq += __shfl_xor_sync(0xffffffffu, sq, o);
        }
        if (j0 == 0) {
            float mean = s * (1.f / SDIM);
            float var  = sq * (1.f / SDIM) - mean * mean;
            stats[row * 2]     = mean;
            stats[row * 2 + 1] = rsqrtf(var + 1e-6f);
        }
    }
    __syncthreads();
    // ---- LN1 pass2: normalize, pre-round ----
    {
        int row = tid >> 3, j0 = tid & 7;
        float mean = stats[row * 2], rstd = stats[row * 2 + 1];
        float4* Xr = (float4*)(Xs + row * ROWST);
        #pragma unroll
        for (int i = 0; i < 16; i++) {
            int c4 = j0 + i * 8;
            float4 v = Xr[c4];
            float4 gv = ((const float4*)ln1g)[c4];
            float4 bv = ((const float4*)ln1b)[c4];
            v.x = rndtf((v.x - mean) * rstd * gv.x + bv.x);
            v.y = rndtf((v.y - mean) * rstd * gv.y + bv.y);
            v.z = rndtf((v.z - mean) * rstd * gv.z + bv.z);
            v.w = rndtf((v.w - mean) * rstd * gv.w + bv.w);
            Xr[c4] = v;
        }
    }
    __syncthreads();

    // ---- GEMM5: Y = out1 @ Wsn ----
    #pragma unroll
    for (int mi = 0; mi < 2; mi++)
        #pragma unroll
        for (int nj = 0; nj < 8; nj++)
            #pragma unroll
            for (int c = 0; c < 4; c++) acc[mi][nj][c] = 0.f;

    mma_block_scalar<ROWST, 64>(acc, Xs, wsnpW, mg, g, t);
    __syncthreads();

    // ---- epilogue 2: relu(acc/sigma) -> Xs ----
    {
        float invsig = g_inv_sigma;
        #pragma unroll
        for (int mi = 0; mi < 2; mi++) {
            int r0 = mg * 32 + mi * 16 + g, r1 = r0 + 8;
            #pragma unroll
            for (int nj = 0; nj < 8; nj++) {
                int c0 = ng * 64 + nj * 8 + 2 * t;          // FIX: ng*64 (was ng*32)
                Xs[r0 * ROWST + c0]     = fmaxf(acc[mi][nj][0] * invsig, 0.f);
                Xs[r0 * ROWST + c0 + 1] = fmaxf(acc[mi][nj][1] * invsig, 0.f);
                Xs[r1 * ROWST + c0]     = fmaxf(acc[mi][nj][2] * invsig, 0.f);
                Xs[r1 * ROWST + c0 + 1] = fmaxf(acc[mi][nj][3] * invsig, 0.f);
            }
        }
    }
    __syncthreads();

    // ---- LN2 pass1 ----
    {
        int row = tid >> 3, j0 = tid & 7;
        const float4* Xr = (const float4*)(Xs + row * ROWST);
        float s = 0.f, sq = 0.f;
        #pragma unroll
        for (int i = 0; i < 16; i++) {
            float4 v = Xr[j0 + i * 8];
            s  += (v.x + v.y) + (v.z + v.w);
            sq += (v.x * v.x + v.y * v.y) + (v.z * v.z + v.w * v.w);
        }
        #pragma unroll
        for (int o = 1; o <= 4; o <<= 1) {
            s  += __shfl_xor_sync(0xffffffffu, s, o);
            sq += __shfl_xor_sync(0xffffffffu, sq, o);
        }
        if (j0 == 0) {
            float mean = s * (1.f / SDIM);
            float var  = sq * (1.f / SDIM) - mean * mean;
            stats[row * 2]     = mean;
            stats[row * 2 + 1] = rsqrtf(var + 1e-6f);
        }
    }
    __syncthreads();
    // ---- LN2 pass2 -> global out ----
    {
        int row = tid >> 3, j0 = tid & 7;
        float mean = stats[row * 2], rstd = stats[row * 2 + 1];
        const float4* Xr = (const float4*)(Xs + row * ROWST);
        float4* orow = (float4*)(out + base + (size_t)row * SDIM);
        #pragma unroll
        for (int i = 0; i < 16; i++) {
            int c4 = j0 + i * 8;
            float4 v = Xr[c4];
            float4 gv = ((const float4*)ln2g)[c4];
            float4 bv = ((const float4*)ln2b)[c4];
            v.x = (v.x - mean) * rstd * gv.x + bv.x;
            v.y = (v.y - mean) * rstd * gv.y + bv.y;
            v.z = (v.z - mean) * rstd * gv.z + bv.z;
            v.w = (v.w - mean) * rstd * gv.w + bv.w;
            orow[c4] = v;
        }
    }
}

// ---------------------------------------------------------------------------
extern "C" void kernel_launch(void* const* d_in, const int* in_sizes, int n_in,
                              void* d_out, int out_size) {
    (void)in_sizes; (void)n_in; (void)out_size;
    const float* x    = (const float*)d_in[0];
    const float* wf   = (const float*)d_in[1];
    const float* bf   = (const float*)d_in[2];
    const float* wg   = (const float*)d_in[3];
    const float* bg   = (const float*)d_in[4];
    const float* wh   = (const float*)d_in[5];
    const float* bh   = (const float*)d_in[6];
    const float* gam  = (const float*)d_in[7];
    const float* ln1g = (const float*)d_in[8];
    const float* ln1b = (const float*)d_in[9];
    const float* wsn  = (const float*)d_in[10];
    const float* usn  = (const float*)d_in[11];
    const float* ln2g = (const float*)d_in[12];
    const float* ln2b = (const float*)d_in[13];
    float* out = (float*)d_out;

    init_kernel<<<513, 512>>>(wf, wg, wh, wsn, usn);

    const int smem_bytes = SM_TOT * 4;
    cudaFuncSetAttribute(fused_kernel, cudaFuncAttributeMaxDynamicSharedMemorySize, smem_bytes);
    fused_kernel<<<1024, 512, smem_bytes>>>(x, bf, bg, bh, gam,
                                            ln1g, ln1b, ln2g, ln2b, out);
}